// round 15
// baseline (speedup 1.0000x reference)
#include <cuda_runtime.h>
#include <cuda_bf16.h>
#include <math.h>
#include <stdint.h>

#define BB 8
#define NN 1024
#define DD 64
#define FIN 256
#define NEGV (-9000000000000000.0f)

// ================= portable PTX helpers (sm_80+) =================
__device__ __forceinline__ uint32_t smem_to_u32(const void* smem_ptr) {
    uint32_t addr;
    asm("{ .reg .u64 tmp; cvta.to.shared.u64 tmp, %1; cvt.u32.u64 %0, tmp; }"
        : "=r"(addr) : "l"(smem_ptr));
    return addr;
}
__device__ __forceinline__ void cp16(uint32_t dst, const void* src) {
    asm volatile("cp.async.cg.shared.global [%0], [%1], 16;" :: "r"(dst), "l"(src));
}
__device__ __forceinline__ void ldsm4(uint32_t &r0, uint32_t &r1, uint32_t &r2, uint32_t &r3,
                                      uint32_t addr) {
    asm volatile("ldmatrix.sync.aligned.m8n8.x4.shared.b16 {%0,%1,%2,%3}, [%4];"
                 : "=r"(r0), "=r"(r1), "=r"(r2), "=r"(r3) : "r"(addr));
}
__device__ __forceinline__ void mma16816(float* c, const uint32_t* a, const uint32_t* b) {
    asm volatile("mma.sync.aligned.m16n8k16.row.col.f32.bf16.bf16.f32 "
                 "{%0,%1,%2,%3}, {%4,%5,%6,%7}, {%8,%9}, {%0,%1,%2,%3};"
                 : "+f"(c[0]), "+f"(c[1]), "+f"(c[2]), "+f"(c[3])
                 : "r"(a[0]), "r"(a[1]), "r"(a[2]), "r"(a[3]), "r"(b[0]), "r"(b[1]));
}

// FFMA-only 2^tt for tt <= 0 (rel err ~2e-6)
__device__ __forceinline__ float exp2_poly(float tt) {
    tt = fmaxf(tt, -125.0f);
    float fn = tt + 12582912.0f;
    int   n  = __float_as_int(fn) - 0x4B400000;
    float f  = tt - (fn - 12582912.0f);
    float p = fmaf(f, 0.00133335581f, 0.00961812911f);
    p = fmaf(f, p, 0.0555041087f);
    p = fmaf(f, p, 0.240226507f);
    p = fmaf(f, p, 0.693147181f);
    p = fmaf(f, p, 1.0f);
    return __int_as_float(__float_as_int(p) + (n << 23));
}
__device__ __forceinline__ float expnegsqrt(float d2) {
    float xh = 0.5f * d2;
    float y = __int_as_float(0x5f3759df - (__float_as_int(d2) >> 1));
    y = y * (1.5f - xh * y * y);
    y = y * (1.5f - xh * y * y);
    y = y * (1.5f - xh * y * y);
    float s = d2 * y;
    return exp2_poly(-s * 1.44269504f);
}
__device__ __forceinline__ float frsqrt(float x) {
    float y = __int_as_float(0x5f3759df - (__float_as_int(x) >> 1));
    y = y * (1.5f - 0.5f * x * y * y);
    y = y * (1.5f - 0.5f * x * y * y);
    y = y * (1.5f - 0.5f * x * y * y);
    return y;
}

// ================= scratch =================
__device__ float  g_h[BB*NN*DD];
__device__ float  g_sq[BB*NN];
__device__ float  g_Wh1[BB*NN];
__device__ float  g_Wh2[BB*NN];
__device__ float  g_A[(size_t)BB*NN*NN];   // E
__device__ float  g_A2[(size_t)BB*NN*NN];  // F2 (exact path only)
__device__ float  g_M[(size_t)BB*NN*NN];   // fallback only
__device__ __nv_bfloat16 g_Fhi[(size_t)BB*NN*NN];
__device__ __nv_bfloat16 g_Flo[(size_t)BB*NN*NN];
__device__ float  g_rowsum[BB*NN];
__device__ float  g_Ediag[BB*NN];
__device__ float  g_rsd[BB*NN];
__device__ float  g_Fdiag[BB*NN];
__device__ float  g_sig[BB*NN];
__device__ float  g_rmax[BB*NN];
__device__ float  g_Q[BB*NN];
__device__ float  g_R[BB*NN];
__device__ float  g_F2s[BB*NN];
__device__ float  g_T1[BB*NN];
__device__ float  g_Fip[BB*NN];
__device__ float  g_diag[BB*NN];
__device__ float  g_sdiag[BB*NN];
__device__ float  g_thr[BB];
__device__ int    g_fastflag[BB];     // may be updated by exact thr
__device__ int    g_fastapprox[BB];   // snapshot from certified bound (never changed)
__device__ int    g_needexact[BB];
__device__ double g_sum[NN];
__device__ double g_sumsq[NN];
// analytic-stats path
__device__ float  g_sw[BB*NN];
__device__ double g_P1[BB*NN];
__device__ double g_P2[BB*NN];
__device__ float  g_w2max[BB];

__device__ __forceinline__ int allfastA() {
    int a = 1;
#pragma unroll
    for (int b = 0; b < BB; b++) a &= g_fastapprox[b];
    return a;
}

// ================= h = x@W, sq, Wh1, Wh2 (4 rows/block) =================
__global__ __launch_bounds__(256) void k_h(const float* __restrict__ x,
                                           const float* __restrict__ W,
                                           const float* __restrict__ a) {
    int g = threadIdx.x >> 6, o = threadIdx.x & 63;
    int bn = blockIdx.x * 4 + g;
    __shared__ float xs[4][FIN];
    __shared__ float red3[4][2][3];
    if (o == 0) {
        g_rowsum[bn] = 0.0f;
        if (bn < NN) { g_sum[bn] = 0.0; g_sumsq[bn] = 0.0; }
    }
    const float* xrow = x + (size_t)bn * FIN;
    ((float4*)xs[g])[o] = ((const float4*)xrow)[o];
    __syncthreads();
    float acc = 0.0f;
#pragma unroll 8
    for (int k = 0; k < FIN; k++) acc = fmaf(xs[g][k], W[k*DD + o], acc);
    g_h[(size_t)bn*DD + o] = acc;
    float v0 = acc * acc, v1 = acc * a[o], v2 = acc * a[DD + o];
    int lane = o & 31, half = o >> 5;
#pragma unroll
    for (int off = 16; off > 0; off >>= 1) {
        v0 += __shfl_xor_sync(0xffffffff, v0, off);
        v1 += __shfl_xor_sync(0xffffffff, v1, off);
        v2 += __shfl_xor_sync(0xffffffff, v2, off);
    }
    if (lane == 0) { red3[g][half][0] = v0; red3[g][half][1] = v1; red3[g][half][2] = v2; }
    __syncthreads();
    if (o == 0) {
        g_sq[bn]  = red3[g][0][0] + red3[g][1][0];
        g_Wh1[bn] = red3[g][0][1] + red3[g][1][1];
        g_Wh2[bn] = red3[g][0][2] + red3[g][1][2];
    }
}

// ================= E = exp(-dist), SYMMETRIC tiles + mirror + Ediag ==========
__global__ __launch_bounds__(256) void k_gram() {
    int b = blockIdx.y;
    int id = blockIdx.x;
    int ti = 0;
    while (id >= 16 - ti) { id -= 16 - ti; ti++; }
    int tj = ti + id;
    int n0 = ti * 64, m0 = tj * 64;
    __shared__ float aT[64][68];
    __shared__ float bT[64][68];
    __shared__ float colsum[64];
    const float* hb = g_h + (size_t)b * NN * DD;
    int t = threadIdx.x;
#pragma unroll
    for (int i = 0; i < 4; i++) {
        int r  = (t >> 4) + i * 16;
        int k4 = (t & 15);
        float4 v = *(const float4*)&hb[(size_t)(n0 + r)*DD + k4*4];
        aT[k4*4+0][r] = v.x; aT[k4*4+1][r] = v.y; aT[k4*4+2][r] = v.z; aT[k4*4+3][r] = v.w;
        float4 w = *(const float4*)&hb[(size_t)(m0 + r)*DD + k4*4];
        bT[k4*4+0][r] = w.x; bT[k4*4+1][r] = w.y; bT[k4*4+2][r] = w.z; bT[k4*4+3][r] = w.w;
    }
    __syncthreads();
    int tx = t & 15, ty = t >> 4;
    float acc[4][4] = {};
#pragma unroll
    for (int k = 0; k < 64; k++) {
        float av[4], bv[4];
        *(float4*)av = *(float4*)&aT[k][ty*4];
        *(float4*)bv = *(float4*)&bT[k][tx*4];
#pragma unroll
        for (int i = 0; i < 4; i++)
#pragma unroll
            for (int j = 0; j < 4; j++) acc[i][j] = fmaf(av[i], bv[j], acc[i][j]);
    }
    __syncthreads();
    float (*stage)[65] = reinterpret_cast<float(*)[65]>(&aT[0][0]);
    if (t < 64) colsum[t] = 0.0f;
    __syncthreads();
    float* Ab = g_A + (size_t)b * NN * NN;
    bool diag = (ti == tj);
    float cs[4] = {0.0f, 0.0f, 0.0f, 0.0f};
#pragma unroll
    for (int i = 0; i < 4; i++) {
        int n = n0 + ty*4 + i;
        float sqn = g_sq[b*NN + n];
        float vv[4];
        float rs = 0.0f;
#pragma unroll
        for (int j = 0; j < 4; j++) {
            int m = m0 + tx*4 + j;
            float d2 = sqn + g_sq[b*NN + m] - 2.0f * acc[i][j];
            float v = (d2 > 0.0f) ? expnegsqrt(d2) : 1.0f;
            vv[j] = v;
            rs += v;
            cs[j] += v;
            stage[ty*4+i][tx*4+j] = v;
            if (diag && n == m) g_Ediag[b*NN + n] = v;
        }
        *(float4*)&Ab[(size_t)n*NN + m0 + tx*4] = make_float4(vv[0], vv[1], vv[2], vv[3]);
        atomicAdd(&g_rowsum[b*NN + n], rs);
    }
    if (!diag) {
#pragma unroll
        for (int j = 0; j < 4; j++) atomicAdd(&colsum[tx*4 + j], cs[j]);
    }
    __syncthreads();
    if (!diag) {
        int r = t >> 2, c0 = (t & 3) * 16;
        float o[16];
#pragma unroll
        for (int q = 0; q < 16; q++) o[q] = stage[c0 + q][r];
        float4* dst = (float4*)&Ab[(size_t)(m0 + r)*NN + n0 + c0];
#pragma unroll
        for (int q = 0; q < 4; q++)
            dst[q] = make_float4(o[q*4], o[q*4+1], o[q*4+2], o[q*4+3]);
        if (t < 64) atomicAdd(&g_rowsum[b*NN + m0 + t], colsum[t]);
    }
}

// ================= O(N^2) row stats: register-only weights ====================
#define DROWS 4
__global__ __launch_bounds__(256) void k_diagx() {
    int b = blockIdx.y;
    int r0 = blockIdx.x * DROWS;
    int t = threadIdx.x;
    float4 rw = ((const float4*)(g_rowsum + b*NN))[t];
    float4 ed = ((const float4*)(g_Ediag + b*NN))[t];
    float rja[4], fda[4];
    {
        float rv[4] = {rw.x, rw.y, rw.z, rw.w};
        float evv[4] = {ed.x, ed.y, ed.z, ed.w};
#pragma unroll
        for (int c = 0; c < 4; c++) {
            float y = frsqrt(fmaxf(rv[c], 1e-12f));
            rja[c] = y;
            fda[c] = evv[c] * y * y;
        }
    }
    const float* Eb = g_A + (size_t)b*NN*NN;
    float ri[DROWS+1];
#pragma unroll
    for (int k = 0; k <= DROWS; k++) {
        int rr = r0 + k; if (rr > NN-1) rr = NN-1;
        ri[k] = frsqrt(fmaxf(g_rowsum[b*NN + rr], 1e-12f));
    }
    float4 e4[DROWS+1];
#pragma unroll
    for (int k = 0; k <= DROWS; k++) {
        int rr = r0 + k; if (rr > NN-1) rr = NN-1;
        e4[k] = ((const float4*)(Eb + (size_t)rr*NN))[t];
    }
    float acc[DROWS][6] = {};
#pragma unroll
    for (int c = 0; c < 4; c++) {
        int j = 4*t + c;
        float rj = rja[c], fdj = fda[c];
        float e[DROWS+1];
        e[0] = (&e4[0].x)[c]; e[1] = (&e4[1].x)[c]; e[2] = (&e4[2].x)[c];
        e[3] = (&e4[3].x)[c]; e[4] = (&e4[4].x)[c];
#pragma unroll
        for (int k = 0; k < DROWS; k++) {
            int i = r0 + k;
            float f0 = e[k] * ri[k] * rj;
            float f1 = e[k+1] * ri[k+1] * rj;
            float s0 = (j != i) ? f0 : 0.0f;
            acc[k][0] += s0;
            acc[k][1] = fmaxf(acc[k][1], s0);
            acc[k][2] = fmaf(s0, s0, acc[k][2]);
            acc[k][3] = fmaf(fdj, s0*s0, acc[k][3]);
            acc[k][4] = fmaf(f0, f1, acc[k][4]);
            acc[k][5] = fmaf(fdj, f0*f1, acc[k][5]);
        }
    }
    __shared__ float wred[8][24];
    int lane = t & 31, wid = t >> 5;
#pragma unroll
    for (int k = 0; k < DROWS; k++)
#pragma unroll
        for (int s = 0; s < 6; s++) {
            float v = acc[k][s];
#pragma unroll
            for (int off = 16; off > 0; off >>= 1) {
                float o = __shfl_xor_sync(0xffffffff, v, off);
                v = (s == 1) ? fmaxf(v, o) : (v + o);
            }
            if (lane == 0) wred[wid][k*6+s] = v;
        }
    __syncthreads();
    if (t < 24) {
        int k = t / 6, s = t % 6;
        float v = wred[0][t];
#pragma unroll
        for (int w = 1; w < 8; w++)
            v = (s == 1) ? fmaxf(v, wred[w][t]) : (v + wred[w][t]);
        int o = b*NN + r0 + k;
        switch (s) {
            case 0: g_sig[o] = v; break;
            case 1: g_rmax[o] = v; break;
            case 2: g_Q[o] = v; break;
            case 3: g_R[o] = v; break;
            case 4: g_F2s[o] = v; break;
            case 5: g_T1[o] = v; break;
        }
    } else if (t < 24 + DROWS) {
        int k = t - 24;
        int i = r0 + k;
        float ri0 = frsqrt(fmaxf(g_rowsum[b*NN + i], 1e-12f));
        g_rsd[b*NN + i] = ri0;
        g_Fdiag[b*NN + i] = g_Ediag[b*NN + i] * ri0 * ri0;
        float fip = 0.0f;
        if (i < NN-1) {
            float ri1 = frsqrt(fmaxf(g_rowsum[b*NN + i + 1], 1e-12f));
            fip = Eb[(size_t)i*NN + i + 1] * ri0 * ri1;
        }
        g_Fip[b*NN + i] = fip;
    }
}

// ================= certified thr upper bound, fast/exact decision =============
__global__ __launch_bounds__(256) void k_thr_approx() {
    int b = blockIdx.x;
    int t = threadIdx.x;
    int o0 = b*NN;
    __shared__ float red[256], red2[256];
    float sm = 0.0f, mm = 0.0f;
    for (int i = t; i < NN; i += 256) {
        sm = fmaxf(sm, g_sig[o0+i]);
        mm = fmaxf(mm, g_rmax[o0+i]);
    }
    red[t] = sm; red2[t] = mm; __syncthreads();
    for (int st = 128; st > 0; st >>= 1) {
        if (t < st) { red[t]=fmaxf(red[t],red[t+st]); red2[t]=fmaxf(red2[t],red2[t+st]); }
        __syncthreads();
    }
    float sigmax = red[0], m = red2[0];
    __syncthreads();
    float mindhi = 3.4e38f, ssum = 0.0f;
    for (int i = t; i < NN; i += 256) {
        float Fii = g_Fdiag[o0+i];
        float Qi = g_Q[o0+i], Ri = g_R[o0+i];
        float base = Fii + 0.8f*(Fii*Fii + Qi)
                   + 0.64f*(Fii*Fii*Fii + 2.0f*Fii*Qi + Ri);
        float Bd = 0.64f * g_sig[o0+i] * sigmax * m;
        mindhi = fminf(mindhi, base + Bd);
        if (i < NN-1) {
            float Fip = g_Fip[o0+i];
            float F2s = g_F2s[o0+i];
            float Fjj = g_Fdiag[o0+i+1];
            float P = F2s - Fip * (Fii + Fjj);
            float W = Fip + 0.8f*F2s
                    + 0.64f*(g_T1[o0+i] + (Fii+Fjj)*P + Fii*Fjj*Fip);
            float rr = g_rsd[o0+i] / g_rsd[o0+i+1];
            float qq = 0.5f * (rr + 1.0f/rr);
            float shi = qq * (W + 0.64f * g_sig[o0+i] * sigmax * m);
            ssum += base - shi;
        }
    }
    red[t] = mindhi; red2[t] = ssum; __syncthreads();
    for (int st = 128; st > 0; st >>= 1) {
        if (t < st) { red[t]=fminf(red[t],red[t+st]); red2[t]+=red2[t+st]; }
        __syncthreads();
    }
    if (t == 0) {
        float thr_hi = red[0] - red2[0] / (float)(NN-1);
        int fast = (thr_hi < -1e-3f) ? 1 : 0;
        g_fastflag[b] = fast;
        g_fastapprox[b] = fast;
        g_needexact[b] = fast ? 0 : 1;
        g_thr[b] = thr_hi;
    }
}

// ================= sort w2 per batch + double prefix sums =====================
__global__ __launch_bounds__(1024) void k_sortw2() {
    int b = blockIdx.x;
    int t = threadIdx.x;
    __shared__ float s[NN];
    __shared__ double p1[NN];
    __shared__ double p2[NN];
    s[t] = g_Wh2[b*NN + t];
    __syncthreads();
    for (int k = 2; k <= NN; k <<= 1) {
        for (int j = k >> 1; j > 0; j >>= 1) {
            int ixj = t ^ j;
            if (ixj > t) {
                float a = s[t], c = s[ixj];
                bool asc = ((t & k) == 0);
                if ((a > c) == asc) { s[t] = c; s[ixj] = a; }
            }
            __syncthreads();
        }
    }
    p1[t] = (double)s[t];
    p2[t] = (double)s[t] * (double)s[t];
    __syncthreads();
    for (int off = 1; off < NN; off <<= 1) {
        double a1 = (t >= off) ? p1[t-off] : 0.0;
        double a2 = (t >= off) ? p2[t-off] : 0.0;
        __syncthreads();
        p1[t] += a1; p2[t] += a2;
        __syncthreads();
    }
    g_sw[b*NN + t] = s[t];
    g_P1[b*NN + t] = p1[t];
    g_P2[b*NN + t] = p2[t];
    if (t == NN-1) g_w2max[b] = s[t];
}

// ================= FAST: fused stats + BN + softmax output (8 rows/block) =====
__global__ __launch_bounds__(256) void k_out(float* __restrict__ out) {
    if (!allfastA()) return;
    int b = blockIdx.y;
    int n0 = blockIdx.x * 8;
    int t = threadIdx.x;
    int lane = t & 31, wid = t >> 5;
    __shared__ float w2s[NN];
    __shared__ float redw[8];
    __shared__ float sinv;
    __shared__ float sh_mean[8], sh_rstd[8];
    ((float4*)w2s)[t] = ((const float4*)(g_Wh2 + b*NN))[t];
    if (t < 8) {
        int n = n0 + t;
        double S = 0.0, S2 = 0.0;
        for (int bb = 0; bb < BB; bb++) {
            float s = g_Wh1[bb*NN + n];
            const float* swb = g_sw + bb*NN;
            int lo = 0, hi = NN;
            while (lo < hi) { int mid = (lo+hi) >> 1; if (swb[mid] < -s) lo = mid+1; else hi = mid; }
            int k = lo;
            double T1 = g_P1[bb*NN + NN-1], T2 = g_P2[bb*NN + NN-1];
            double n1 = k ? g_P1[bb*NN + k-1] : 0.0;
            double n2 = k ? g_P2[bb*NN + k-1] : 0.0;
            double pz1 = T1 - n1, pz2 = T2 - n2;
            double sd = (double)s;
            S  += 0.01*(k*sd + n1) + ((NN-k)*sd + pz1);
            S2 += 1e-4*(k*sd*sd + 2.0*sd*n1 + n2) + ((NN-k)*sd*sd + 2.0*sd*pz1 + pz2);
        }
        double cnt = (double)(BB*NN);
        double mean = S / cnt;
        double var = S2 / cnt - mean*mean;
        if (var < 0.0) var = 0.0;
        sh_mean[t] = (float)mean;
        sh_rstd[t] = (float)(1.0 / sqrt(var + 1e-5));
    }
    float w2m = g_w2max[b];
    __syncthreads();
    for (int rr = 0; rr < 8; rr++) {
        int n = n0 + rr;
        float s = g_Wh1[b*NN + n];
        float mean = sh_mean[rr], rstd = sh_rstd[rr];
        float emax = s + w2m;
        emax = (emax >= 0.0f) ? emax : 0.01f * emax;
        float zmax = (emax - mean) * rstd;
        float4 wv = ((float4*)w2s)[t];
        float p[4];
        float sum = 0.0f;
#pragma unroll
        for (int i = 0; i < 4; i++) {
            float e = s + (&wv.x)[i];
            e = (e >= 0.0f) ? e : 0.01f * e;
            p[i] = exp2_poly(((e - mean) * rstd - zmax) * 1.44269504f);
            sum += p[i];
        }
#pragma unroll
        for (int off = 16; off > 0; off >>= 1) sum += __shfl_xor_sync(0xffffffff, sum, off);
        if (lane == 0) redw[wid] = sum;
        __syncthreads();
        if (t == 0) {
            float tot = 0.0f;
#pragma unroll
            for (int w = 0; w < 8; w++) tot += redw[w];
            sinv = 1.0f / tot;
        }
        __syncthreads();
        float si = sinv;
        float* row = out + ((size_t)b*NN + n) * NN;
        ((float4*)row)[t] = make_float4(p[0]*si, p[1]*si, p[2]*si, p[3]*si);
        __syncthreads();
    }
}

// ================= EXACT PATH (guarded): F split =================
__global__ void k_splitF() {
    size_t i = (size_t)blockIdx.x * blockDim.x + threadIdx.x;
    int bidx = (int)(i >> 18);
    if (!g_needexact[bidx]) return;
    float4 v = ((float4*)g_A)[i];
    int row  = (int)(i >> 8);
    int col  = (int)(i & 255) * 4;
    int base = (row >> 10) << 10;
    float ri = g_rsd[row];
    v.x *= ri * g_rsd[base + col + 0];
    v.y *= ri * g_rsd[base + col + 1];
    v.z *= ri * g_rsd[base + col + 2];
    v.w *= ri * g_rsd[base + col + 3];
    __nv_bfloat16 h0 = __float2bfloat16(v.x), h1 = __float2bfloat16(v.y);
    __nv_bfloat16 h2 = __float2bfloat16(v.z), h3 = __float2bfloat16(v.w);
    __nv_bfloat16 l0 = __float2bfloat16(v.x - __bfloat162float(h0));
    __nv_bfloat16 l1 = __float2bfloat16(v.y - __bfloat162float(h1));
    __nv_bfloat16 l2 = __float2bfloat16(v.z - __bfloat162float(h2));
    __nv_bfloat16 l3 = __float2bfloat16(v.w - __bfloat162float(h3));
    __nv_bfloat162 hp0(h0, h1), hp1(h2, h3), lp0(l0, l1), lp1(l2, l3);
    uint2 hv, lv;
    hv.x = *(uint32_t*)&hp0; hv.y = *(uint32_t*)&hp1;
    lv.x = *(uint32_t*)&lp0; lv.y = *(uint32_t*)&lp1;
    ((uint2*)g_Fhi)[i] = hv;
    ((uint2*)g_Flo)[i] = lv;
}

// ================= EXACT PATH: mma.sync SYRK + fused mirror =================
#define KCH 32
#define SROW 40
#define TILEB (128 * SROW * 2)
#define STAGEB (4 * TILEB)
#define SMEM_MMA (2 * STAGEB)

__global__ __launch_bounds__(256, 2) void k_syrk_mma() {
    int b = blockIdx.y;
    if (!g_needexact[b]) return;
    extern __shared__ __align__(16) char smem[];
    uint32_t sbase = smem_to_u32(smem);
    int id = blockIdx.x;
    int ti = 0;
    while (id >= 8 - ti) { id -= 8 - ti; ti++; }
    int tj = ti + id;
    int row0 = ti * 128, col0 = tj * 128;
    int tid = threadIdx.x;
    int lane = tid & 31, wid = tid >> 5;
    int wr = wid >> 2, wc = wid & 3;

    const __nv_bfloat16* FhiB = g_Fhi + (size_t)b * NN * NN;
    const __nv_bfloat16* FloB = g_Flo + (size_t)b * NN * NN;

    int prow[8], pc4[8], ptile[8];
#pragma unroll
    for (int i = 0; i < 8; i++) {
        int idx = tid + i * 256;
        ptile[i] = idx >> 9;
        int w = idx & 511;
        prow[i] = w >> 2;
        pc4[i]  = w & 3;
    }
    auto issue = [&](int chunk, int stage) {
        int k0 = chunk * KCH;
#pragma unroll
        for (int i = 0; i < 8; i++) {
            int gr = ((ptile[i] & 2) ? col0 : row0) + prow[i];
            const __nv_bfloat16* bp = (ptile[i] & 1) ? FloB : FhiB;
            cp16(sbase + stage*STAGEB + ptile[i]*TILEB
                     + (uint32_t)(prow[i]*SROW + pc4[i]*8) * 2,
                 bp + (size_t)gr * NN + k0 + pc4[i] * 8);
        }
        asm volatile("cp.async.commit_group;" ::: "memory");
    };

    float acc[4][4][4];
#pragma unroll
    for (int mt = 0; mt < 4; mt++)
#pragma unroll
        for (int nt = 0; nt < 4; nt++)
#pragma unroll
            for (int q = 0; q < 4; q++) acc[mt][nt][q] = 0.0f;

    issue(0, 0);
    const int NCH = NN / KCH;
    for (int c = 0; c < NCH; c++) {
        int buf = c & 1;
        if (c + 1 < NCH) {
            issue(c + 1, buf ^ 1);
            asm volatile("cp.async.wait_group 1;" ::: "memory");
        } else {
            asm volatile("cp.async.wait_group 0;" ::: "memory");
        }
        __syncthreads();
        uint32_t tb = sbase + buf * STAGEB;
        int arow = lane & 15;
        int acolh = (lane >> 4) << 3;
        int bm = lane >> 3;
        int brow = ((bm >> 1) << 3) + (lane & 7);
        int bcolh = (bm & 1) << 3;

#pragma unroll
        for (int ks = 0; ks < 2; ks++) {
            int kofs = ks * 16;
            uint32_t bh[4][2], bl[4][2];
#pragma unroll
            for (int p = 0; p < 2; p++) {
                uint32_t off = (uint32_t)((wc*32 + p*16 + brow) * SROW + kofs + bcolh) * 2;
                uint32_t r0, r1, r2, r3;
                ldsm4(r0, r1, r2, r3, tb + 2*TILEB + off);
                bh[p*2][0] = r0; bh[p*2][1] = r1; bh[p*2+1][0] = r2; bh[p*2+1][1] = r3;
                ldsm4(r0, r1, r2, r3, tb + 3*TILEB + off);
                bl[p*2][0] = r0; bl[p*2][1] = r1; bl[p*2+1][0] = r2; bl[p*2+1][1] = r3;
            }
#pragma unroll
            for (int mt = 0; mt < 4; mt++) {
                uint32_t ah[4], al[4];
                uint32_t off = (uint32_t)((wr*64 + mt*16 + arow) * SROW + kofs + acolh) * 2;
                ldsm4(ah[0], ah[1], ah[2], ah[3], tb + 0*TILEB + off);
                ldsm4(al[0], al[1], al[2], al[3], tb + 1*TILEB + off);
#pragma unroll
                for (int nt = 0; nt < 4; nt++) {
                    mma16816(acc[mt][nt], ah, bh[nt]);
                    mma16816(acc[mt][nt], ah, bl[nt]);
                    mma16816(acc[mt][nt], al, bh[nt]);
                }
            }
        }
        __syncthreads();
    }

    float* Cb = g_A2 + (size_t)b * NN * NN;
#pragma unroll
    for (int mt = 0; mt < 4; mt++) {
        int r = row0 + wr*64 + mt*16 + (lane >> 2);
#pragma unroll
        for (int nt = 0; nt < 4; nt++) {
            int cc = col0 + wc*32 + nt*8 + (lane & 3)*2;
            *(float2*)&Cb[(size_t)r*NN + cc]     = make_float2(acc[mt][nt][0], acc[mt][nt][1]);
            *(float2*)&Cb[(size_t)(r+8)*NN + cc] = make_float2(acc[mt][nt][2], acc[mt][nt][3]);
        }
    }
    if (ti != tj) {
        float* stg = (float*)smem;
        __syncthreads();
#pragma unroll
        for (int mt = 0; mt < 4; mt++) {
            int rl = wr*64 + mt*16 + (lane >> 2);
#pragma unroll
            for (int nt = 0; nt < 4; nt++) {
                int cl = wc*32 + nt*8 + (lane & 3)*2;
                stg[rl*133 + cl]       = acc[mt][nt][0];
                stg[rl*133 + cl + 1]   = acc[mt][nt][1];
                stg[(rl+8)*133 + cl]   = acc[mt][nt][2];
                stg[(rl+8)*133 + cl+1] = acc[mt][nt][3];
            }
        }
        __syncthreads();
        int oc = tid >> 1, half = tid & 1;
#pragma unroll
        for (int q = 0; q < 16; q++) {
            int rr = half*64 + q*4;
            float4 v = make_float4(stg[(rr+0)*133 + oc], stg[(rr+1)*133 + oc],
                                   stg[(rr+2)*133 + oc], stg[(rr+3)*133 + oc]);
            *(float4*)&Cb[(size_t)(col0 + oc)*NN + row0 + rr] = v;
        }
    }
}

// ================= EXACT PATH: diag/superdiag =================
__global__ __launch_bounds__(256) void k_diag() {
    int i = blockIdx.x, b = blockIdx.y;
    if (!g_needexact[b]) return;
    int t = threadIdx.x;
    const __nv_bfloat16* hi = g_Fhi + (size_t)b * NN * NN;
    const __nv_bfloat16* lo = g_Flo + (size_t)b * NN * NN;
    const float* F2b = g_A2 + (size_t)b * NN * NN;
    bool hn = (i < NN - 1);
    int i1 = i + (hn ? 1 : 0);
    const float* f2row = &F2b[(size_t)i*NN];
    const __nv_bfloat16 *h0r = hi + (size_t)i*NN,  *l0r = lo + (size_t)i*NN;
    const __nv_bfloat16 *h1r = hi + (size_t)i1*NN, *l1r = lo + (size_t)i1*NN;
    float s0 = 0.0f, s1 = 0.0f;
    for (int j = t; j < NN; j += 256) {
        float f2 = f2row[j];
        float f0 = __bfloat162float(h0r[j]) + __bfloat162float(l0r[j]);
        float f1 = __bfloat162float(h1r[j]) + __bfloat162float(l1r[j]);
        s0 = fmaf(f2, f0, s0);
        s1 = fmaf(f2, f1, s1);
    }
    __shared__ float r0[256], r1[256];
    r0[t] = s0; r1[t] = s1; __syncthreads();
    for (int st = 128; st > 0; st >>= 1) {
        if (t < st) { r0[t] += r0[t+st]; r1[t] += r1[t+st]; }
        __syncthreads();
    }
    if (t == 0) {
        float fii = __bfloat162float(h0r[i]) + __bfloat162float(l0r[i]);
        g_diag[b*NN + i] = fii + 0.8f*f2row[i] + 0.64f*r0[0];
        if (hn) {
            float fip = __bfloat162float(h0r[i+1]) + __bfloat162float(l0r[i+1]);
            float r = g_rsd[b*NN + i] / g_rsd[b*NN + i + 1];
            float q = 0.5f * (r + 1.0f/r);
            g_sdiag[b*NN + i] = q * (fip + 0.8f*f2row[i+1] + 0.64f*r1[0]);
        }
    }
}

// ================= EXACT PATH: thr =================
__global__ __launch_bounds__(256) void k_thr_exact() {
    int b = blockIdx.x;
    if (!g_needexact[b]) return;
    int t = threadIdx.x;
    __shared__ float smin[256];
    __shared__ float ssum[256];
    float mn = 3.4e38f, s = 0.0f;
    for (int n = t; n < NN; n += 256) mn = fminf(mn, g_diag[b*NN + n]);
    for (int n = t; n < NN-1; n += 256) s += g_diag[b*NN + n] - g_sdiag[b*NN + n];
    smin[t] = mn; ssum[t] = s; __syncthreads();
    for (int st = 128; st > 0; st >>= 1) {
        if (t < st) { smin[t] = fminf(smin[t], smin[t+st]); ssum[t] += ssum[t+st]; }
        __syncthreads();
    }
    if (t == 0) {
        float thr = smin[0] - ssum[0] / (float)(NN-1);
        g_thr[b] = thr;
        g_fastflag[b] = (thr < 0.0f) ? 1 : 0;
    }
}

// ================= FALLBACK: M = scale(F + .8F2 + .64 F@F2) =================
__global__ __launch_bounds__(256) void k_gemm_fb() {
    int b = blockIdx.z;
    if (!g_needexact[b] || g_fastflag[b]) return;
    __shared__ float As[2][8][128];
    __shared__ float Bs[2][8][128];
    const float* Eb = g_A  + (size_t)b * NN * NN;
    const float* Bb = g_A2 + (size_t)b * NN * NN;
    float*       Cb = g_M  + (size_t)b * NN * NN;
    const float* rsd = g_rsd + b * NN;

    int t = threadIdx.x;
    int tx = t & 15, ty = t >> 4;
    int row0 = blockIdx.y * 128, col0 = blockIdx.x * 128;
    int lar = t >> 1, lak = (t & 1) * 4;
    int lbk = t >> 5, lbc = (t & 31) * 4;
    float rsdr = rsd[row0 + lar];

    float4 av = *(const float4*)&Eb[(size_t)(row0 + lar)*NN + lak];
    float4 bv = *(const float4*)&Bb[(size_t)lbk*NN + col0 + lbc];
    As[0][lak+0][lar] = av.x * rsdr * rsd[lak+0];
    As[0][lak+1][lar] = av.y * rsdr * rsd[lak+1];
    As[0][lak+2][lar] = av.z * rsdr * rsd[lak+2];
    As[0][lak+3][lar] = av.w * rsdr * rsd[lak+3];
    *(float4*)&Bs[0][lbk][lbc] = bv;
    __syncthreads();

    float acc[8][8] = {};
    const int nk = NN / 8;
    for (int kt = 0; kt < nk; kt++) {
        int cur = kt & 1, nxt = cur ^ 1;
        int k0 = (kt + 1) * 8;
        if (kt + 1 < nk) {
            av = *(const float4*)&Eb[(size_t)(row0 + lar)*NN + k0 + lak];
            bv = *(const float4*)&Bb[(size_t)(k0 + lbk)*NN + col0 + lbc];
        }
#pragma unroll
        for (int kk = 0; kk < 8; kk++) {
            float af[8], bf[8];
            *(float4*)&af[0] = *(float4*)&As[cur][kk][ty*8];
            *(float4*)&af[4] = *(float4*)&As[cur][kk][ty*8+4];
            *(float4*)&bf[0] = *(float4*)&Bs[cur][kk][tx*8];
            *(float4*)&bf[4] = *(float4*)&Bs[cur][kk][tx*8+4];
#pragma unroll
            for (int i = 0; i < 8; i++)
#pragma unroll
                for (int j = 0; j < 8; j++) acc[i][j] = fmaf(af[i], bf[j], acc[i][j]);
        }
        if (kt + 1 < nk) {
            As[nxt][lak+0][lar] = av.x * rsdr * rsd[k0+lak+0];
            As[nxt][lak+1][lar] = av.y * rsdr * rsd[k0+lak+1];
            As[nxt][lak+2][lar] = av.z * rsdr * rsd[k0+lak+2];
            As[nxt][lak+3][lar] = av.w * rsdr * rsd[k0+lak+3];
            *(float4*)&Bs[nxt][lbk][lbc] = bv;
            __syncthreads();
        }
    }
#pragma unroll
    for (int i = 0; i < 8; i++) {
        int r = row0 + ty*8 + i;
        float ri = rsd[r];
#pragma unroll
        for (int j = 0; j < 8; j++) {
            int c = col0 + tx*8 + j;
            size_t idx = (size_t)r*NN + c;
            float Fv = Eb[idx] * ri * rsd[c];
            float scale = ri / rsd[c];
            Cb[idx] = scale * (Fv + 0.8f*Bb[idx] + 0.64f*acc[i][j]);
        }
    }
}

// ================= FALLBACK: symmetrize M =================
__global__ __launch_bounds__(1024) void k_symm() {
    int ti = blockIdx.x, tj = blockIdx.y, b = blockIdx.z;
    if (!g_needexact[b] || g_fastflag[b]) return;
    if (tj < ti) return;
    __shared__ float s1[32][33];
    __shared__ float s2[32][33];
    float* Mb = g_M + (size_t)b * NN * NN;
    int tx = threadIdx.x, ty = threadIdx.y;
    int r1 = ti*32 + ty, c1 = tj*32 + tx;
    int r2 = tj*32 + ty, c2 = ti*32 + tx;
    s1[ty][tx] = Mb[(size_t)r1*NN + c1];
    s2[ty][tx] = Mb[(size_t)r2*NN + c2];
    __syncthreads();
    Mb[(size_t)r1*NN + c1] = 0.5f * (s1[ty][tx] + s2[tx][ty]);
    if (ti != tj)
        Mb[(size_t)r2*NN + c2] = 0.5f * (s2[ty][tx] + s1[tx][ty]);
}

// ================= MIXED/EXACT: att stats =================
__global__ __launch_bounds__(256) void k_att(float* __restrict__ out) {
    if (allfastA()) return;
    int n = blockIdx.x, b = blockIdx.y;
    int t = threadIdx.x;
    float w1  = g_Wh1[b*NN + n];
    float thr = g_thr[b];
    int fast  = g_fastflag[b];
    const float* Mrow = g_M + ((size_t)b*NN + n) * NN;
    float*       Orow = out + ((size_t)b*NN + n) * NN;
    __shared__ float ws[NN];
    for (int m = t; m < NN; m += 256) ws[m] = g_Wh2[b*NN + m];
    __syncthreads();
    double s = 0.0, ss = 0.0;
    for (int m = t; m < NN; m += 256) {
        float e = w1 + ws[m];
        e = (e >= 0.0f) ? e : 0.01f * e;
        float att;
        if (fast) att = e;
        else { att = (Mrow[m] > thr) ? e : NEGV; Orow[m] = att; }
        s  += (double)att;
        ss += (double)att * (double)att;
    }
    __shared__ double ds[256];
    __shared__ double dss[256];
    ds[t] = s; dss[t] = ss; __syncthreads();
    for (int st = 128; st > 0; st >>= 1) {
        if (t < st) { ds[t] += ds[t+st]; dss[t] += dss[t+st]; }
        __syncthreads();
    }
    if (t == 0) {
        atomicAdd(&g_sum[n], ds[0]);
        atomicAdd(&g_sumsq[n], dss[0]);
    }
}

// ================= MIXED/EXACT: BN stats + softmax =================
__global__ __launch_bounds__(256) void k_softmax(float* __restrict__ out) {
    if (allfastA()) return;
    int n = blockIdx.x, b = blockIdx.y;
    int t = threadIdx.x;
    __shared__ float s_mean, s_rstd;
    if (t == 0) {
        double cnt = (double)(BB * NN);
        double mean = g_sum[n] / cnt;
        double var  = g_sumsq[n] / cnt - mean * mean;
        if (var < 0.0) var = 0.0;
        s_mean = (float)mean;
        s_rstd = (float)(1.0 / sqrt(var + 1e-5));
    }
    __syncthreads();
    float mean = s_mean, rstd = s_rstd;
    int fast = g_fastflag[b];
    float w1 = g_Wh1[b*NN + n];
    float* row = out + ((size_t)b*NN + n) * NN;
    __shared__ float ws[NN];
    if (fast) {
        for (int m = t; m < NN; m += 256) ws[m] = g_Wh2[b*NN + m];
        __syncthreads();
    }
    float z[4];
    float mx = -3.4e38f;
#pragma unroll
    for (int i = 0; i < 4; i++) {
        int m = t + i*256;
        float attv;
        if (fast) {
            float e = w1 + ws[m];
            attv = (e >= 0.0f) ? e : 0.01f * e;
        } else attv = row[m];
        float v = (attv - mean) * rstd;
        z[i] = v;
        mx = fmaxf(mx, v);
    }
    __shared__ float red[256];
    red[t] = mx; __syncthreads();
    for (int st = 128; st > 0; st >>= 1) {
        if (t < st) red[t] = fmaxf(red[t], red[t+st]);
        __syncthreads();
    }
    mx = red[0]; __syncthreads();
    float sum = 0.0f;
#pragma unroll
    for (int i = 0; i < 4; i++) {
        z[i] = expf(z[i] - mx);
        sum += z[i];
    }
    red[t] = sum; __syncthreads();
    for (int st = 128; st > 0; st >>= 1) {
        if (t < st) red[t] += red[t+st];
        __syncthreads();
    }
    sum = red[0];
#pragma unroll
    for (int i = 0; i < 4; i++) row[t + i*256] = z[i] / sum;
}

// ================= launch =================
extern "C" void kernel_launch(void* const* d_in, const int* in_sizes, int n_in,
                              void* d_out, int out_size) {
    const float* x = (const float*)d_in[0];
    const float* W = (const float*)d_in[1];
    const float* a = (const float*)d_in[2];
    float* out = (float*)d_out;

    static cudaStream_t s1 = nullptr, s2 = nullptr;
    static cudaEvent_t ev_h = nullptr, ev_thr = nullptr, ev_exact = nullptr, ev_sort = nullptr;
    static int inited = 0;
    if (!inited) {
        cudaFuncSetAttribute(k_syrk_mma, cudaFuncAttributeMaxDynamicSharedMemorySize, SMEM_MMA);
        cudaStreamCreateWithFlags(&s1, cudaStreamNonBlocking);
        cudaStreamCreateWithFlags(&s2, cudaStreamNonBlocking);
        cudaEventCreateWithFlags(&ev_h, cudaEventDisableTiming);
        cudaEventCreateWithFlags(&ev_thr, cudaEventDisableTiming);
        cudaEventCreateWithFlags(&ev_exact, cudaEventDisableTiming);
        cudaEventCreateWithFlags(&ev_sort, cudaEventDisableTiming);
        inited = 1;
    }

    // main stream: h -> gram -> diagx -> thr_approx -> out
    k_h<<<2048, 256>>>(x, W, a);
    cudaEventRecord(ev_h, 0);
    cudaStreamWaitEvent(s2, ev_h, 0);
    k_sortw2<<<BB, 1024, 0, s2>>>();
    cudaEventRecord(ev_sort, s2);

    k_gram<<<dim3(136, BB), 256>>>();
    k_diagx<<<dim3(256, BB), 256>>>();
    k_thr_approx<<<BB, 256>>>();
    cudaEventRecord(ev_thr, 0);

    // s1: exact chain + mixed output (all no-ops when certified fast)
    cudaStreamWaitEvent(s1, ev_thr, 0);
    k_splitF<<<8192, 256, 0, s1>>>();
    k_syrk_mma<<<dim3(36, BB), 256, SMEM_MMA, s1>>>();
    k_diag<<<dim3(NN, BB), 256, 0, s1>>>();
    k_thr_exact<<<BB, 256, 0, s1>>>();
    k_gemm_fb<<<dim3(8, 8, BB), 256, 0, s1>>>();
    k_symm<<<dim3(32, 32, BB), dim3(32, 32), 0, s1>>>();
    k_att<<<dim3(NN, BB), 256, 0, s1>>>(out);
    k_softmax<<<dim3(NN, BB), 256, 0, s1>>>(out);
    cudaEventRecord(ev_exact, s1);

    // main: fast output, then join s1
    cudaStreamWaitEvent(0, ev_sort, 0);
    k_out<<<dim3(128, BB), 256>>>(out);
    cudaStreamWaitEvent(0, ev_exact, 0);
}

// round 16
// speedup vs baseline: 1.6307x; 1.6307x over previous
#include <cuda_runtime.h>
#include <cuda_bf16.h>
#include <math.h>
#include <stdint.h>

#define BB 8
#define NN 1024
#define DD 64
#define FIN 256
#define NEGV (-9000000000000000.0f)

// ================= portable PTX helpers (sm_80+) =================
__device__ __forceinline__ uint32_t smem_to_u32(const void* smem_ptr) {
    uint32_t addr;
    asm("{ .reg .u64 tmp; cvta.to.shared.u64 tmp, %1; cvt.u32.u64 %0, tmp; }"
        : "=r"(addr) : "l"(smem_ptr));
    return addr;
}
__device__ __forceinline__ void cp16(uint32_t dst, const void* src) {
    asm volatile("cp.async.cg.shared.global [%0], [%1], 16;" :: "r"(dst), "l"(src));
}
__device__ __forceinline__ void ldsm4(uint32_t &r0, uint32_t &r1, uint32_t &r2, uint32_t &r3,
                                      uint32_t addr) {
    asm volatile("ldmatrix.sync.aligned.m8n8.x4.shared.b16 {%0,%1,%2,%3}, [%4];"
                 : "=r"(r0), "=r"(r1), "=r"(r2), "=r"(r3) : "r"(addr));
}
__device__ __forceinline__ void mma16816(float* c, const uint32_t* a, const uint32_t* b) {
    asm volatile("mma.sync.aligned.m16n8k16.row.col.f32.bf16.bf16.f32 "
                 "{%0,%1,%2,%3}, {%4,%5,%6,%7}, {%8,%9}, {%0,%1,%2,%3};"
                 : "+f"(c[0]), "+f"(c[1]), "+f"(c[2]), "+f"(c[3])
                 : "r"(a[0]), "r"(a[1]), "r"(a[2]), "r"(a[3]), "r"(b[0]), "r"(b[1]));
}

// FFMA-only 2^tt for tt <= 0 (rel err ~2e-6)
__device__ __forceinline__ float exp2_poly(float tt) {
    tt = fmaxf(tt, -125.0f);
    float fn = tt + 12582912.0f;
    int   n  = __float_as_int(fn) - 0x4B400000;
    float f  = tt - (fn - 12582912.0f);
    float p = fmaf(f, 0.00133335581f, 0.00961812911f);
    p = fmaf(f, p, 0.0555041087f);
    p = fmaf(f, p, 0.240226507f);
    p = fmaf(f, p, 0.693147181f);
    p = fmaf(f, p, 1.0f);
    return __int_as_float(__float_as_int(p) + (n << 23));
}
__device__ __forceinline__ float expnegsqrt(float d2) {
    float xh = 0.5f * d2;
    float y = __int_as_float(0x5f3759df - (__float_as_int(d2) >> 1));
    y = y * (1.5f - xh * y * y);
    y = y * (1.5f - xh * y * y);
    y = y * (1.5f - xh * y * y);
    float s = d2 * y;
    return exp2_poly(-s * 1.44269504f);
}
__device__ __forceinline__ float frsqrt(float x) {
    float y = __int_as_float(0x5f3759df - (__float_as_int(x) >> 1));
    y = y * (1.5f - 0.5f * x * y * y);
    y = y * (1.5f - 0.5f * x * y * y);
    y = y * (1.5f - 0.5f * x * y * y);
    return y;
}

// ================= scratch =================
__device__ float  g_h[BB*NN*DD];
__device__ float  g_sq[BB*NN];
__device__ float  g_Wh1[BB*NN];
__device__ float  g_Wh2[BB*NN];
__device__ float  g_A[(size_t)BB*NN*NN];   // E
__device__ float  g_A2[(size_t)BB*NN*NN];  // F2 (exact path only)
__device__ float  g_M[(size_t)BB*NN*NN];   // fallback only
__device__ __nv_bfloat16 g_Fhi[(size_t)BB*NN*NN];
__device__ __nv_bfloat16 g_Flo[(size_t)BB*NN*NN];
__device__ float  g_rowsum[BB*NN];
__device__ float  g_Ediag[BB*NN];
__device__ float  g_rsd[BB*NN];
__device__ float  g_Fdiag[BB*NN];
__device__ float  g_sig[BB*NN];
__device__ float  g_rmax[BB*NN];
__device__ float  g_Q[BB*NN];
__device__ float  g_R[BB*NN];
__device__ float  g_F2s[BB*NN];
__device__ float  g_T1[BB*NN];
__device__ float  g_Fip[BB*NN];
__device__ float  g_diag[BB*NN];
__device__ float  g_sdiag[BB*NN];
__device__ float  g_thr[BB];
__device__ int    g_fastflag[BB];     // may be updated by exact thr
__device__ int    g_fastapprox[BB];   // snapshot from certified bound (never changed)
__device__ int    g_needexact[BB];
__device__ double g_sum[NN];
__device__ double g_sumsq[NN];
// analytic-stats path
__device__ float  g_sw[BB*NN];
__device__ double g_P1[BB*NN];
__device__ double g_P2[BB*NN];
__device__ float  g_w2max[BB];
__device__ float  g_meanf[NN];
__device__ float  g_rstdf[NN];

__device__ __forceinline__ int allfastA() {
    int a = 1;
#pragma unroll
    for (int b = 0; b < BB; b++) a &= g_fastapprox[b];
    return a;
}

// ================= h = x@W, sq, Wh1, Wh2 (4 rows/block) =================
__global__ __launch_bounds__(256) void k_h(const float* __restrict__ x,
                                           const float* __restrict__ W,
                                           const float* __restrict__ a) {
    int g = threadIdx.x >> 6, o = threadIdx.x & 63;
    int bn = blockIdx.x * 4 + g;
    __shared__ float xs[4][FIN];
    __shared__ float red3[4][2][3];
    if (o == 0) {
        g_rowsum[bn] = 0.0f;
        if (bn < NN) { g_sum[bn] = 0.0; g_sumsq[bn] = 0.0; }
    }
    const float* xrow = x + (size_t)bn * FIN;
    ((float4*)xs[g])[o] = ((const float4*)xrow)[o];
    __syncthreads();
    float acc = 0.0f;
#pragma unroll 8
    for (int k = 0; k < FIN; k++) acc = fmaf(xs[g][k], W[k*DD + o], acc);
    g_h[(size_t)bn*DD + o] = acc;
    float v0 = acc * acc, v1 = acc * a[o], v2 = acc * a[DD + o];
    int lane = o & 31, half = o >> 5;
#pragma unroll
    for (int off = 16; off > 0; off >>= 1) {
        v0 += __shfl_xor_sync(0xffffffff, v0, off);
        v1 += __shfl_xor_sync(0xffffffff, v1, off);
        v2 += __shfl_xor_sync(0xffffffff, v2, off);
    }
    if (lane == 0) { red3[g][half][0] = v0; red3[g][half][1] = v1; red3[g][half][2] = v2; }
    __syncthreads();
    if (o == 0) {
        g_sq[bn]  = red3[g][0][0] + red3[g][1][0];
        g_Wh1[bn] = red3[g][0][1] + red3[g][1][1];
        g_Wh2[bn] = red3[g][0][2] + red3[g][1][2];
    }
}

// ================= E = exp(-dist), SYMMETRIC tiles + mirror + Ediag ==========
__global__ __launch_bounds__(256) void k_gram() {
    int b = blockIdx.y;
    int id = blockIdx.x;
    int ti = 0;
    while (id >= 16 - ti) { id -= 16 - ti; ti++; }
    int tj = ti + id;
    int n0 = ti * 64, m0 = tj * 64;
    __shared__ float aT[64][68];
    __shared__ float bT[64][68];
    __shared__ float colsum[64];
    const float* hb = g_h + (size_t)b * NN * DD;
    int t = threadIdx.x;
#pragma unroll
    for (int i = 0; i < 4; i++) {
        int r  = (t >> 4) + i * 16;
        int k4 = (t & 15);
        float4 v = *(const float4*)&hb[(size_t)(n0 + r)*DD + k4*4];
        aT[k4*4+0][r] = v.x; aT[k4*4+1][r] = v.y; aT[k4*4+2][r] = v.z; aT[k4*4+3][r] = v.w;
        float4 w = *(const float4*)&hb[(size_t)(m0 + r)*DD + k4*4];
        bT[k4*4+0][r] = w.x; bT[k4*4+1][r] = w.y; bT[k4*4+2][r] = w.z; bT[k4*4+3][r] = w.w;
    }
    __syncthreads();
    int tx = t & 15, ty = t >> 4;
    float acc[4][4] = {};
#pragma unroll
    for (int k = 0; k < 64; k++) {
        float av[4], bv[4];
        *(float4*)av = *(float4*)&aT[k][ty*4];
        *(float4*)bv = *(float4*)&bT[k][tx*4];
#pragma unroll
        for (int i = 0; i < 4; i++)
#pragma unroll
            for (int j = 0; j < 4; j++) acc[i][j] = fmaf(av[i], bv[j], acc[i][j]);
    }
    __syncthreads();
    float (*stage)[65] = reinterpret_cast<float(*)[65]>(&aT[0][0]);
    if (t < 64) colsum[t] = 0.0f;
    __syncthreads();
    float* Ab = g_A + (size_t)b * NN * NN;
    bool diag = (ti == tj);
    float cs[4] = {0.0f, 0.0f, 0.0f, 0.0f};
#pragma unroll
    for (int i = 0; i < 4; i++) {
        int n = n0 + ty*4 + i;
        float sqn = g_sq[b*NN + n];
        float vv[4];
        float rs = 0.0f;
#pragma unroll
        for (int j = 0; j < 4; j++) {
            int m = m0 + tx*4 + j;
            float d2 = sqn + g_sq[b*NN + m] - 2.0f * acc[i][j];
            float v = (d2 > 0.0f) ? expnegsqrt(d2) : 1.0f;
            vv[j] = v;
            rs += v;
            cs[j] += v;
            stage[ty*4+i][tx*4+j] = v;
            if (diag && n == m) g_Ediag[b*NN + n] = v;
        }
        *(float4*)&Ab[(size_t)n*NN + m0 + tx*4] = make_float4(vv[0], vv[1], vv[2], vv[3]);
        atomicAdd(&g_rowsum[b*NN + n], rs);
    }
    if (!diag) {
#pragma unroll
        for (int j = 0; j < 4; j++) atomicAdd(&colsum[tx*4 + j], cs[j]);
    }
    __syncthreads();
    if (!diag) {
        int r = t >> 2, c0 = (t & 3) * 16;
        float o[16];
#pragma unroll
        for (int q = 0; q < 16; q++) o[q] = stage[c0 + q][r];
        float4* dst = (float4*)&Ab[(size_t)(m0 + r)*NN + n0 + c0];
#pragma unroll
        for (int q = 0; q < 4; q++)
            dst[q] = make_float4(o[q*4], o[q*4+1], o[q*4+2], o[q*4+3]);
        if (t < 64) atomicAdd(&g_rowsum[b*NN + m0 + t], colsum[t]);
    }
}

// ================= O(N^2) row stats: register-only weights ====================
#define DROWS 4
__global__ __launch_bounds__(256) void k_diagx() {
    int b = blockIdx.y;
    int r0 = blockIdx.x * DROWS;
    int t = threadIdx.x;
    float4 rw = ((const float4*)(g_rowsum + b*NN))[t];
    float4 ed = ((const float4*)(g_Ediag + b*NN))[t];
    float rja[4], fda[4];
    {
        float rv[4] = {rw.x, rw.y, rw.z, rw.w};
        float evv[4] = {ed.x, ed.y, ed.z, ed.w};
#pragma unroll
        for (int c = 0; c < 4; c++) {
            float y = frsqrt(fmaxf(rv[c], 1e-12f));
            rja[c] = y;
            fda[c] = evv[c] * y * y;
        }
    }
    const float* Eb = g_A + (size_t)b*NN*NN;
    float ri[DROWS+1];
#pragma unroll
    for (int k = 0; k <= DROWS; k++) {
        int rr = r0 + k; if (rr > NN-1) rr = NN-1;
        ri[k] = frsqrt(fmaxf(g_rowsum[b*NN + rr], 1e-12f));
    }
    float4 e4[DROWS+1];
#pragma unroll
    for (int k = 0; k <= DROWS; k++) {
        int rr = r0 + k; if (rr > NN-1) rr = NN-1;
        e4[k] = ((const float4*)(Eb + (size_t)rr*NN))[t];
    }
    float acc[DROWS][6] = {};
#pragma unroll
    for (int c = 0; c < 4; c++) {
        int j = 4*t + c;
        float rj = rja[c], fdj = fda[c];
        float e[DROWS+1];
        e[0] = (&e4[0].x)[c]; e[1] = (&e4[1].x)[c]; e[2] = (&e4[2].x)[c];
        e[3] = (&e4[3].x)[c]; e[4] = (&e4[4].x)[c];
#pragma unroll
        for (int k = 0; k < DROWS; k++) {
            int i = r0 + k;
            float f0 = e[k] * ri[k] * rj;
            float f1 = e[k+1] * ri[k+1] * rj;
            float s0 = (j != i) ? f0 : 0.0f;
            acc[k][0] += s0;
            acc[k][1] = fmaxf(acc[k][1], s0);
            acc[k][2] = fmaf(s0, s0, acc[k][2]);
            acc[k][3] = fmaf(fdj, s0*s0, acc[k][3]);
            acc[k][4] = fmaf(f0, f1, acc[k][4]);
            acc[k][5] = fmaf(fdj, f0*f1, acc[k][5]);
        }
    }
    __shared__ float wred[8][24];
    int lane = t & 31, wid = t >> 5;
#pragma unroll
    for (int k = 0; k < DROWS; k++)
#pragma unroll
        for (int s = 0; s < 6; s++) {
            float v = acc[k][s];
#pragma unroll
            for (int off = 16; off > 0; off >>= 1) {
                float o = __shfl_xor_sync(0xffffffff, v, off);
                v = (s == 1) ? fmaxf(v, o) : (v + o);
            }
            if (lane == 0) wred[wid][k*6+s] = v;
        }
    __syncthreads();
    if (t < 24) {
        int k = t / 6, s = t % 6;
        float v = wred[0][t];
#pragma unroll
        for (int w = 1; w < 8; w++)
            v = (s == 1) ? fmaxf(v, wred[w][t]) : (v + wred[w][t]);
        int o = b*NN + r0 + k;
        switch (s) {
            case 0: g_sig[o] = v; break;
            case 1: g_rmax[o] = v; break;
            case 2: g_Q[o] = v; break;
            case 3: g_R[o] = v; break;
            case 4: g_F2s[o] = v; break;
            case 5: g_T1[o] = v; break;
        }
    } else if (t < 24 + DROWS) {
        int k = t - 24;
        int i = r0 + k;
        float ri0 = frsqrt(fmaxf(g_rowsum[b*NN + i], 1e-12f));
        g_rsd[b*NN + i] = ri0;
        g_Fdiag[b*NN + i] = g_Ediag[b*NN + i] * ri0 * ri0;
        float fip = 0.0f;
        if (i < NN-1) {
            float ri1 = frsqrt(fmaxf(g_rowsum[b*NN + i + 1], 1e-12f));
            fip = Eb[(size_t)i*NN + i + 1] * ri0 * ri1;
        }
        g_Fip[b*NN + i] = fip;
    }
}

// ================= certified thr upper bound, fast/exact decision =============
__global__ __launch_bounds__(256) void k_thr_approx() {
    int b = blockIdx.x;
    int t = threadIdx.x;
    int o0 = b*NN;
    __shared__ float red[256], red2[256];
    float sm = 0.0f, mm = 0.0f;
    for (int i = t; i < NN; i += 256) {
        sm = fmaxf(sm, g_sig[o0+i]);
        mm = fmaxf(mm, g_rmax[o0+i]);
    }
    red[t] = sm; red2[t] = mm; __syncthreads();
    for (int st = 128; st > 0; st >>= 1) {
        if (t < st) { red[t]=fmaxf(red[t],red[t+st]); red2[t]=fmaxf(red2[t],red2[t+st]); }
        __syncthreads();
    }
    float sigmax = red[0], m = red2[0];
    __syncthreads();
    float mindhi = 3.4e38f, ssum = 0.0f;
    for (int i = t; i < NN; i += 256) {
        float Fii = g_Fdiag[o0+i];
        float Qi = g_Q[o0+i], Ri = g_R[o0+i];
        float base = Fii + 0.8f*(Fii*Fii + Qi)
                   + 0.64f*(Fii*Fii*Fii + 2.0f*Fii*Qi + Ri);
        float Bd = 0.64f * g_sig[o0+i] * sigmax * m;
        mindhi = fminf(mindhi, base + Bd);
        if (i < NN-1) {
            float Fip = g_Fip[o0+i];
            float F2s = g_F2s[o0+i];
            float Fjj = g_Fdiag[o0+i+1];
            float P = F2s - Fip * (Fii + Fjj);
            float W = Fip + 0.8f*F2s
                    + 0.64f*(g_T1[o0+i] + (Fii+Fjj)*P + Fii*Fjj*Fip);
            float rr = g_rsd[o0+i] / g_rsd[o0+i+1];
            float qq = 0.5f * (rr + 1.0f/rr);
            float shi = qq * (W + 0.64f * g_sig[o0+i] * sigmax * m);
            ssum += base - shi;
        }
    }
    red[t] = mindhi; red2[t] = ssum; __syncthreads();
    for (int st = 128; st > 0; st >>= 1) {
        if (t < st) { red[t]=fminf(red[t],red[t+st]); red2[t]+=red2[t+st]; }
        __syncthreads();
    }
    if (t == 0) {
        float thr_hi = red[0] - red2[0] / (float)(NN-1);
        int fast = (thr_hi < -1e-3f) ? 1 : 0;
        g_fastflag[b] = fast;
        g_fastapprox[b] = fast;
        g_needexact[b] = fast ? 0 : 1;
        g_thr[b] = thr_hi;
    }
}

// ================= sort w2 per batch + double prefix sums =====================
__global__ __launch_bounds__(1024) void k_sortw2() {
    int b = blockIdx.x;
    int t = threadIdx.x;
    __shared__ float s[NN];
    __shared__ double p1[NN];
    __shared__ double p2[NN];
    s[t] = g_Wh2[b*NN + t];
    __syncthreads();
    for (int k = 2; k <= NN; k <<= 1) {
        for (int j = k >> 1; j > 0; j >>= 1) {
            int ixj = t ^ j;
            if (ixj > t) {
                float a = s[t], c = s[ixj];
                bool asc = ((t & k) == 0);
                if ((a > c) == asc) { s[t] = c; s[ixj] = a; }
            }
            __syncthreads();
        }
    }
    p1[t] = (double)s[t];
    p2[t] = (double)s[t] * (double)s[t];
    __syncthreads();
    for (int off = 1; off < NN; off <<= 1) {
        double a1 = (t >= off) ? p1[t-off] : 0.0;
        double a2 = (t >= off) ? p2[t-off] : 0.0;
        __syncthreads();
        p1[t] += a1; p2[t] += a2;
        __syncthreads();
    }
    g_sw[b*NN + t] = s[t];
    g_P1[b*NN + t] = p1[t];
    g_P2[b*NN + t] = p2[t];
    if (t == NN-1) g_w2max[b] = s[t];
}

// ================= analytic BN stats (off critical path, on s2) ===============
__global__ __launch_bounds__(256) void k_stats_fast() {
    int n = blockIdx.x * 256 + threadIdx.x;
    double S = 0.0, S2 = 0.0;
    for (int bb = 0; bb < BB; bb++) {
        float s = g_Wh1[bb*NN + n];
        const float* swb = g_sw + bb*NN;
        int lo = 0, hi = NN;
        while (lo < hi) { int mid = (lo+hi) >> 1; if (swb[mid] < -s) lo = mid+1; else hi = mid; }
        int k = lo;
        double T1 = g_P1[bb*NN + NN-1], T2 = g_P2[bb*NN + NN-1];
        double n1 = k ? g_P1[bb*NN + k-1] : 0.0;
        double n2 = k ? g_P2[bb*NN + k-1] : 0.0;
        double pz1 = T1 - n1, pz2 = T2 - n2;
        double sd = (double)s;
        S  += 0.01*(k*sd + n1) + ((NN-k)*sd + pz1);
        S2 += 1e-4*(k*sd*sd + 2.0*sd*n1 + n2) + ((NN-k)*sd*sd + 2.0*sd*pz1 + pz2);
    }
    double cnt = (double)(BB*NN);
    double mean = S / cnt;
    double var = S2 / cnt - mean*mean;
    if (var < 0.0) var = 0.0;
    g_meanf[n] = (float)mean;
    g_rstdf[n] = (float)(1.0 / sqrt(var + 1e-5));
}

// ================= FAST: fused BN + softmax output (4 rows/block) =============
__global__ __launch_bounds__(256) void k_out(float* __restrict__ out) {
    if (!allfastA()) return;
    int b = blockIdx.y;
    int n0 = blockIdx.x * 4;
    int t = threadIdx.x;
    int lane = t & 31, wid = t >> 5;
    __shared__ float w2s[NN];
    __shared__ float redw[8];
    __shared__ float sinv;
    ((float4*)w2s)[t] = ((const float4*)(g_Wh2 + b*NN))[t];
    float w2m = g_w2max[b];
    __syncthreads();
    for (int rr = 0; rr < 4; rr++) {
        int n = n0 + rr;
        float s = g_Wh1[b*NN + n];
        float mean = g_meanf[n], rstd = g_rstdf[n];
        float emax = s + w2m;
        emax = (emax >= 0.0f) ? emax : 0.01f * emax;
        float zmax = (emax - mean) * rstd;
        float4 wv = ((float4*)w2s)[t];
        float p[4];
        float sum = 0.0f;
#pragma unroll
        for (int i = 0; i < 4; i++) {
            float e = s + (&wv.x)[i];
            e = (e >= 0.0f) ? e : 0.01f * e;
            p[i] = exp2_poly(((e - mean) * rstd - zmax) * 1.44269504f);
            sum += p[i];
        }
#pragma unroll
        for (int off = 16; off > 0; off >>= 1) sum += __shfl_xor_sync(0xffffffff, sum, off);
        if (lane == 0) redw[wid] = sum;
        __syncthreads();
        if (t == 0) {
            float tot = 0.0f;
#pragma unroll
            for (int w = 0; w < 8; w++) tot += redw[w];
            sinv = 1.0f / tot;
        }
        __syncthreads();
        float si = sinv;
        float* row = out + ((size_t)b*NN + n) * NN;
        ((float4*)row)[t] = make_float4(p[0]*si, p[1]*si, p[2]*si, p[3]*si);
        __syncthreads();
    }
}

// ================= EXACT PATH (guarded): F split =================
__global__ void k_splitF() {
    size_t i = (size_t)blockIdx.x * blockDim.x + threadIdx.x;
    int bidx = (int)(i >> 18);
    if (!g_needexact[bidx]) return;
    float4 v = ((float4*)g_A)[i];
    int row  = (int)(i >> 8);
    int col  = (int)(i & 255) * 4;
    int base = (row >> 10) << 10;
    float ri = g_rsd[row];
    v.x *= ri * g_rsd[base + col + 0];
    v.y *= ri * g_rsd[base + col + 1];
    v.z *= ri * g_rsd[base + col + 2];
    v.w *= ri * g_rsd[base + col + 3];
    __nv_bfloat16 h0 = __float2bfloat16(v.x), h1 = __float2bfloat16(v.y);
    __nv_bfloat16 h2 = __float2bfloat16(v.z), h3 = __float2bfloat16(v.w);
    __nv_bfloat16 l0 = __float2bfloat16(v.x - __bfloat162float(h0));
    __nv_bfloat16 l1 = __float2bfloat16(v.y - __bfloat162float(h1));
    __nv_bfloat16 l2 = __float2bfloat16(v.z - __bfloat162float(h2));
    __nv_bfloat16 l3 = __float2bfloat16(v.w - __bfloat162float(h3));
    __nv_bfloat162 hp0(h0, h1), hp1(h2, h3), lp0(l0, l1), lp1(l2, l3);
    uint2 hv, lv;
    hv.x = *(uint32_t*)&hp0; hv.y = *(uint32_t*)&hp1;
    lv.x = *(uint32_t*)&lp0; lv.y = *(uint32_t*)&lp1;
    ((uint2*)g_Fhi)[i] = hv;
    ((uint2*)g_Flo)[i] = lv;
}

// ================= EXACT PATH: mma.sync SYRK + fused mirror =================
#define KCH 32
#define SROW 40
#define TILEB (128 * SROW * 2)
#define STAGEB (4 * TILEB)
#define SMEM_MMA (2 * STAGEB)

__global__ __launch_bounds__(256, 2) void k_syrk_mma() {
    int b = blockIdx.y;
    if (!g_needexact[b]) return;
    extern __shared__ __align__(16) char smem[];
    uint32_t sbase = smem_to_u32(smem);
    int id = blockIdx.x;
    int ti = 0;
    while (id >= 8 - ti) { id -= 8 - ti; ti++; }
    int tj = ti + id;
    int row0 = ti * 128, col0 = tj * 128;
    int tid = threadIdx.x;
    int lane = tid & 31, wid = tid >> 5;
    int wr = wid >> 2, wc = wid & 3;

    const __nv_bfloat16* FhiB = g_Fhi + (size_t)b * NN * NN;
    const __nv_bfloat16* FloB = g_Flo + (size_t)b * NN * NN;

    int prow[8], pc4[8], ptile[8];
#pragma unroll
    for (int i = 0; i < 8; i++) {
        int idx = tid + i * 256;
        ptile[i] = idx >> 9;
        int w = idx & 511;
        prow[i] = w >> 2;
        pc4[i]  = w & 3;
    }
    auto issue = [&](int chunk, int stage) {
        int k0 = chunk * KCH;
#pragma unroll
        for (int i = 0; i < 8; i++) {
            int gr = ((ptile[i] & 2) ? col0 : row0) + prow[i];
            const __nv_bfloat16* bp = (ptile[i] & 1) ? FloB : FhiB;
            cp16(sbase + stage*STAGEB + ptile[i]*TILEB
                     + (uint32_t)(prow[i]*SROW + pc4[i]*8) * 2,
                 bp + (size_t)gr * NN + k0 + pc4[i] * 8);
        }
        asm volatile("cp.async.commit_group;" ::: "memory");
    };

    float acc[4][4][4];
#pragma unroll
    for (int mt = 0; mt < 4; mt++)
#pragma unroll
        for (int nt = 0; nt < 4; nt++)
#pragma unroll
            for (int q = 0; q < 4; q++) acc[mt][nt][q] = 0.0f;

    issue(0, 0);
    const int NCH = NN / KCH;
    for (int c = 0; c < NCH; c++) {
        int buf = c & 1;
        if (c + 1 < NCH) {
            issue(c + 1, buf ^ 1);
            asm volatile("cp.async.wait_group 1;" ::: "memory");
        } else {
            asm volatile("cp.async.wait_group 0;" ::: "memory");
        }
        __syncthreads();
        uint32_t tb = sbase + buf * STAGEB;
        int arow = lane & 15;
        int acolh = (lane >> 4) << 3;
        int bm = lane >> 3;
        int brow = ((bm >> 1) << 3) + (lane & 7);
        int bcolh = (bm & 1) << 3;

#pragma unroll
        for (int ks = 0; ks < 2; ks++) {
            int kofs = ks * 16;
            uint32_t bh[4][2], bl[4][2];
#pragma unroll
            for (int p = 0; p < 2; p++) {
                uint32_t off = (uint32_t)((wc*32 + p*16 + brow) * SROW + kofs + bcolh) * 2;
                uint32_t r0, r1, r2, r3;
                ldsm4(r0, r1, r2, r3, tb + 2*TILEB + off);
                bh[p*2][0] = r0; bh[p*2][1] = r1; bh[p*2+1][0] = r2; bh[p*2+1][1] = r3;
                ldsm4(r0, r1, r2, r3, tb + 3*TILEB + off);
                bl[p*2][0] = r0; bl[p*2][1] = r1; bl[p*2+1][0] = r2; bl[p*2+1][1] = r3;
            }
#pragma unroll
            for (int mt = 0; mt < 4; mt++) {
                uint32_t ah[4], al[4];
                uint32_t off = (uint32_t)((wr*64 + mt*16 + arow) * SROW + kofs + acolh) * 2;
                ldsm4(ah[0], ah[1], ah[2], ah[3], tb + 0*TILEB + off);
                ldsm4(al[0], al[1], al[2], al[3], tb + 1*TILEB + off);
#pragma unroll
                for (int nt = 0; nt < 4; nt++) {
                    mma16816(acc[mt][nt], ah, bh[nt]);
                    mma16816(acc[mt][nt], ah, bl[nt]);
                    mma16816(acc[mt][nt], al, bh[nt]);
                }
            }
        }
        __syncthreads();
    }

    float* Cb = g_A2 + (size_t)b * NN * NN;
#pragma unroll
    for (int mt = 0; mt < 4; mt++) {
        int r = row0 + wr*64 + mt*16 + (lane >> 2);
#pragma unroll
        for (int nt = 0; nt < 4; nt++) {
            int cc = col0 + wc*32 + nt*8 + (lane & 3)*2;
            *(float2*)&Cb[(size_t)r*NN + cc]     = make_float2(acc[mt][nt][0], acc[mt][nt][1]);
            *(float2*)&Cb[(size_t)(r+8)*NN + cc] = make_float2(acc[mt][nt][2], acc[mt][nt][3]);
        }
    }
    if (ti != tj) {
        float* stg = (float*)smem;
        __syncthreads();
#pragma unroll
        for (int mt = 0; mt < 4; mt++) {
            int rl = wr*64 + mt*16 + (lane >> 2);
#pragma unroll
            for (int nt = 0; nt < 4; nt++) {
                int cl = wc*32 + nt*8 + (lane & 3)*2;
                stg[rl*133 + cl]       = acc[mt][nt][0];
                stg[rl*133 + cl + 1]   = acc[mt][nt][1];
                stg[(rl+8)*133 + cl]   = acc[mt][nt][2];
                stg[(rl+8)*133 + cl+1] = acc[mt][nt][3];
            }
        }
        __syncthreads();
        int oc = tid >> 1, half = tid & 1;
#pragma unroll
        for (int q = 0; q < 16; q++) {
            int rr = half*64 + q*4;
            float4 v = make_float4(stg[(rr+0)*133 + oc], stg[(rr+1)*133 + oc],
                                   stg[(rr+2)*133 + oc], stg[(rr+3)*133 + oc]);
            *(float4*)&Cb[(size_t)(col0 + oc)*NN + row0 + rr] = v;
        }
    }
}

// ================= EXACT PATH: diag/superdiag =================
__global__ __launch_bounds__(256) void k_diag() {
    int i = blockIdx.x, b = blockIdx.y;
    if (!g_needexact[b]) return;
    int t = threadIdx.x;
    const __nv_bfloat16* hi = g_Fhi + (size_t)b * NN * NN;
    const __nv_bfloat16* lo = g_Flo + (size_t)b * NN * NN;
    const float* F2b = g_A2 + (size_t)b * NN * NN;
    bool hn = (i < NN - 1);
    int i1 = i + (hn ? 1 : 0);
    const float* f2row = &F2b[(size_t)i*NN];
    const __nv_bfloat16 *h0r = hi + (size_t)i*NN,  *l0r = lo + (size_t)i*NN;
    const __nv_bfloat16 *h1r = hi + (size_t)i1*NN, *l1r = lo + (size_t)i1*NN;
    float s0 = 0.0f, s1 = 0.0f;
    for (int j = t; j < NN; j += 256) {
        float f2 = f2row[j];
        float f0 = __bfloat162float(h0r[j]) + __bfloat162float(l0r[j]);
        float f1 = __bfloat162float(h1r[j]) + __bfloat162float(l1r[j]);
        s0 = fmaf(f2, f0, s0);
        s1 = fmaf(f2, f1, s1);
    }
    __shared__ float r0[256], r1[256];
    r0[t] = s0; r1[t] = s1; __syncthreads();
    for (int st = 128; st > 0; st >>= 1) {
        if (t < st) { r0[t] += r0[t+st]; r1[t] += r1[t+st]; }
        __syncthreads();
    }
    if (t == 0) {
        float fii = __bfloat162float(h0r[i]) + __bfloat162float(l0r[i]);
        g_diag[b*NN + i] = fii + 0.8f*f2row[i] + 0.64f*r0[0];
        if (hn) {
            float fip = __bfloat162float(h0r[i+1]) + __bfloat162float(l0r[i+1]);
            float r = g_rsd[b*NN + i] / g_rsd[b*NN + i + 1];
            float q = 0.5f * (r + 1.0f/r);
            g_sdiag[b*NN + i] = q * (fip + 0.8f*f2row[i+1] + 0.64f*r1[0]);
        }
    }
}

// ================= EXACT PATH: thr =================
__global__ __launch_bounds__(256) void k_thr_exact() {
    int b = blockIdx.x;
    if (!g_needexact[b]) return;
    int t = threadIdx.x;
    __shared__ float smin[256];
    __shared__ float ssum[256];
    float mn = 3.4e38f, s = 0.0f;
    for (int n = t; n < NN; n += 256) mn = fminf(mn, g_diag[b*NN + n]);
    for (int n = t; n < NN-1; n += 256) s += g_diag[b*NN + n] - g_sdiag[b*NN + n];
    smin[t] = mn; ssum[t] = s; __syncthreads();
    for (int st = 128; st > 0; st >>= 1) {
        if (t < st) { smin[t] = fminf(smin[t], smin[t+st]); ssum[t] += ssum[t+st]; }
        __syncthreads();
    }
    if (t == 0) {
        float thr = smin[0] - ssum[0] / (float)(NN-1);
        g_thr[b] = thr;
        g_fastflag[b] = (thr < 0.0f) ? 1 : 0;
    }
}

// ================= FALLBACK: M = scale(F + .8F2 + .64 F@F2) =================
__global__ __launch_bounds__(256) void k_gemm_fb() {
    int b = blockIdx.z;
    if (!g_needexact[b] || g_fastflag[b]) return;
    __shared__ float As[2][8][128];
    __shared__ float Bs[2][8][128];
    const float* Eb = g_A  + (size_t)b * NN * NN;
    const float* Bb = g_A2 + (size_t)b * NN * NN;
    float*       Cb = g_M  + (size_t)b * NN * NN;
    const float* rsd = g_rsd + b * NN;

    int t = threadIdx.x;
    int tx = t & 15, ty = t >> 4;
    int row0 = blockIdx.y * 128, col0 = blockIdx.x * 128;
    int lar = t >> 1, lak = (t & 1) * 4;
    int lbk = t >> 5, lbc = (t & 31) * 4;
    float rsdr = rsd[row0 + lar];

    float4 av = *(const float4*)&Eb[(size_t)(row0 + lar)*NN + lak];
    float4 bv = *(const float4*)&Bb[(size_t)lbk*NN + col0 + lbc];
    As[0][lak+0][lar] = av.x * rsdr * rsd[lak+0];
    As[0][lak+1][lar] = av.y * rsdr * rsd[lak+1];
    As[0][lak+2][lar] = av.z * rsdr * rsd[lak+2];
    As[0][lak+3][lar] = av.w * rsdr * rsd[lak+3];
    *(float4*)&Bs[0][lbk][lbc] = bv;
    __syncthreads();

    float acc[8][8] = {};
    const int nk = NN / 8;
    for (int kt = 0; kt < nk; kt++) {
        int cur = kt & 1, nxt = cur ^ 1;
        int k0 = (kt + 1) * 8;
        if (kt + 1 < nk) {
            av = *(const float4*)&Eb[(size_t)(row0 + lar)*NN + k0 + lak];
            bv = *(const float4*)&Bb[(size_t)(k0 + lbk)*NN + col0 + lbc];
        }
#pragma unroll
        for (int kk = 0; kk < 8; kk++) {
            float af[8], bf[8];
            *(float4*)&af[0] = *(float4*)&As[cur][kk][ty*8];
            *(float4*)&af[4] = *(float4*)&As[cur][kk][ty*8+4];
            *(float4*)&bf[0] = *(float4*)&Bs[cur][kk][tx*8];
            *(float4*)&bf[4] = *(float4*)&Bs[cur][kk][tx*8+4];
#pragma unroll
            for (int i = 0; i < 8; i++)
#pragma unroll
                for (int j = 0; j < 8; j++) acc[i][j] = fmaf(af[i], bf[j], acc[i][j]);
        }
        if (kt + 1 < nk) {
            As[nxt][lak+0][lar] = av.x * rsdr * rsd[k0+lak+0];
            As[nxt][lak+1][lar] = av.y * rsdr * rsd[k0+lak+1];
            As[nxt][lak+2][lar] = av.z * rsdr * rsd[k0+lak+2];
            As[nxt][lak+3][lar] = av.w * rsdr * rsd[k0+lak+3];
            *(float4*)&Bs[nxt][lbk][lbc] = bv;
            __syncthreads();
        }
    }
#pragma unroll
    for (int i = 0; i < 8; i++) {
        int r = row0 + ty*8 + i;
        float ri = rsd[r];
#pragma unroll
        for (int j = 0; j < 8; j++) {
            int c = col0 + tx*8 + j;
            size_t idx = (size_t)r*NN + c;
            float Fv = Eb[idx] * ri * rsd[c];
            float scale = ri / rsd[c];
            Cb[idx] = scale * (Fv + 0.8f*Bb[idx] + 0.64f*acc[i][j]);
        }
    }
}

// ================= FALLBACK: symmetrize M =================
__global__ __launch_bounds__(1024) void k_symm() {
    int ti = blockIdx.x, tj = blockIdx.y, b = blockIdx.z;
    if (!g_needexact[b] || g_fastflag[b]) return;
    if (tj < ti) return;
    __shared__ float s1[32][33];
    __shared__ float s2[32][33];
    float* Mb = g_M + (size_t)b * NN * NN;
    int tx = threadIdx.x, ty = threadIdx.y;
    int r1 = ti*32 + ty, c1 = tj*32 + tx;
    int r2 = tj*32 + ty, c2 = ti*32 + tx;
    s1[ty][tx] = Mb[(size_t)r1*NN + c1];
    s2[ty][tx] = Mb[(size_t)r2*NN + c2];
    __syncthreads();
    Mb[(size_t)r1*NN + c1] = 0.5f * (s1[ty][tx] + s2[tx][ty]);
    if (ti != tj)
        Mb[(size_t)r2*NN + c2] = 0.5f * (s2[ty][tx] + s1[tx][ty]);
}

// ================= MIXED/EXACT: att stats =================
__global__ __launch_bounds__(256) void k_att(float* __restrict__ out) {
    if (allfastA()) return;
    int n = blockIdx.x, b = blockIdx.y;
    int t = threadIdx.x;
    float w1  = g_Wh1[b*NN + n];
    float thr = g_thr[b];
    int fast  = g_fastflag[b];
    const float* Mrow = g_M + ((size_t)b*NN + n) * NN;
    float*       Orow = out + ((size_t)b*NN + n) * NN;
    __shared__ float ws[NN];
    for (int m = t; m < NN; m += 256) ws[m] = g_Wh2[b*NN + m];
    __syncthreads();
    double s = 0.0, ss = 0.0;
    for (int m = t; m < NN; m += 256) {
        float e = w1 + ws[m];
        e = (e >= 0.0f) ? e : 0.01f * e;
        float att;
        if (fast) att = e;
        else { att = (Mrow[m] > thr) ? e : NEGV; Orow[m] = att; }
        s  += (double)att;
        ss += (double)att * (double)att;
    }
    __shared__ double ds[256];
    __shared__ double dss[256];
    ds[t] = s; dss[t] = ss; __syncthreads();
    for (int st = 128; st > 0; st >>= 1) {
        if (t < st) { ds[t] += ds[t+st]; dss[t] += dss[t+st]; }
        __syncthreads();
    }
    if (t == 0) {
        atomicAdd(&g_sum[n], ds[0]);
        atomicAdd(&g_sumsq[n], dss[0]);
    }
}

// ================= MIXED/EXACT: BN stats + softmax =================
__global__ __launch_bounds__(256) void k_softmax(float* __restrict__ out) {
    if (allfastA()) return;
    int n = blockIdx.x, b = blockIdx.y;
    int t = threadIdx.x;
    __shared__ float s_mean, s_rstd;
    if (t == 0) {
        double cnt = (double)(BB * NN);
        double mean = g_sum[n] / cnt;
        double var  = g_sumsq[n] / cnt - mean * mean;
        if (var < 0.0) var = 0.0;
        s_mean = (float)mean;
        s_rstd = (float)(1.0 / sqrt(var + 1e-5));
    }
    __syncthreads();
    float mean = s_mean, rstd = s_rstd;
    int fast = g_fastflag[b];
    float w1 = g_Wh1[b*NN + n];
    float* row = out + ((size_t)b*NN + n) * NN;
    __shared__ float ws[NN];
    if (fast) {
        for (int m = t; m < NN; m += 256) ws[m] = g_Wh2[b*NN + m];
        __syncthreads();
    }
    float z[4];
    float mx = -3.4e38f;
#pragma unroll
    for (int i = 0; i < 4; i++) {
        int m = t + i*256;
        float attv;
        if (fast) {
            float e = w1 + ws[m];
            attv = (e >= 0.0f) ? e : 0.01f * e;
        } else attv = row[m];
        float v = (attv - mean) * rstd;
        z[i] = v;
        mx = fmaxf(mx, v);
    }
    __shared__ float red[256];
    red[t] = mx; __syncthreads();
    for (int st = 128; st > 0; st >>= 1) {
        if (t < st) red[t] = fmaxf(red[t], red[t+st]);
        __syncthreads();
    }
    mx = red[0]; __syncthreads();
    float sum = 0.0f;
#pragma unroll
    for (int i = 0; i < 4; i++) {
        z[i] = expf(z[i] - mx);
        sum += z[i];
    }
    red[t] = sum; __syncthreads();
    for (int st = 128; st > 0; st >>= 1) {
        if (t < st) red[t] += red[t+st];
        __syncthreads();
    }
    sum = red[0];
#pragma unroll
    for (int i = 0; i < 4; i++) row[t + i*256] = z[i] / sum;
}

// ================= launch (round-12 layout; stats_fast added on s2) ===========
extern "C" void kernel_launch(void* const* d_in, const int* in_sizes, int n_in,
                              void* d_out, int out_size) {
    const float* x = (const float*)d_in[0];
    const float* W = (const float*)d_in[1];
    const float* a = (const float*)d_in[2];
    float* out = (float*)d_out;

    static cudaStream_t s1 = nullptr, s2 = nullptr;
    static cudaEvent_t ev_h = nullptr, ev_thr = nullptr, ev_exact = nullptr, ev_sort = nullptr;
    static int inited = 0;
    if (!inited) {
        cudaFuncSetAttribute(k_syrk_mma, cudaFuncAttributeMaxDynamicSharedMemorySize, SMEM_MMA);
        cudaStreamCreateWithFlags(&s1, cudaStreamNonBlocking);
        cudaStreamCreateWithFlags(&s2, cudaStreamNonBlocking);
        cudaEventCreateWithFlags(&ev_h, cudaEventDisableTiming);
        cudaEventCreateWithFlags(&ev_thr, cudaEventDisableTiming);
        cudaEventCreateWithFlags(&ev_exact, cudaEventDisableTiming);
        cudaEventCreateWithFlags(&ev_sort, cudaEventDisableTiming);
        inited = 1;
    }

    // main stream: h -> gram -> diagx -> thr_approx
    k_h<<<2048, 256>>>(x, W, a);
    cudaEventRecord(ev_h, 0);
    // s2: sortw2 + analytic stats (depend only on k_h), overlap gram/diagx
    cudaStreamWaitEvent(s2, ev_h, 0);
    k_sortw2<<<BB, 1024, 0, s2>>>();
    k_stats_fast<<<4, 256, 0, s2>>>();
    cudaEventRecord(ev_sort, s2);

    k_gram<<<dim3(136, BB), 256>>>();
    k_diagx<<<dim3(256, BB), 256>>>();
    k_thr_approx<<<BB, 256>>>();
    cudaEventRecord(ev_thr, 0);

    // s1: exact chain (all no-ops when certified fast), overlaps fast output
    cudaStreamWaitEvent(s1, ev_thr, 0);
    k_splitF<<<8192, 256, 0, s1>>>();
    k_syrk_mma<<<dim3(36, BB), 256, SMEM_MMA, s1>>>();
    k_diag<<<dim3(NN, BB), 256, 0, s1>>>();
    k_thr_exact<<<BB, 256, 0, s1>>>();
    k_gemm_fb<<<dim3(8, 8, BB), 256, 0, s1>>>();
    k_symm<<<dim3(32, 32, BB), dim3(32, 32), 0, s1>>>();
    cudaEventRecord(ev_exact, s1);

    // main: fast output (guards on approx snapshot flags)
    cudaStreamWaitEvent(0, ev_sort, 0);
    k_out<<<dim3(256, BB), 256>>>(out);

    // join exact chain, then mixed/exact output
    cudaStreamWaitEvent(0, ev_exact, 0);
    k_att<<<dim3(NN, BB), 256>>>(out);
    k_softmax<<<dim3(NN, BB), 256>>>(out);
}